// round 1
// baseline (speedup 1.0000x reference)
#include <cuda_runtime.h>
#include <math.h>

#define TPB 256
#define SUB 8
#define LCH (TPB * SUB)      // 2048 steps per chunk
#define NCH 2048             // chunks: T / LCH  (T = 4194304)
#define CPT 8                // chunks per thread in scan kernel (NCH / TPB)

// Scratch (device globals: no allocation allowed)
__device__ float g_carry[NCH * 2];
__device__ float g_xstart[NCH * 2];
__device__ float g_M[9 * 4];   // g_M[k] = A^(8 * 2^k), k = 0..8  (g_M[8] = A^2048 = A^LCH)
__device__ float g_dc[2];      // b_A + b_B

// 2x2 row-major matmul: Z = X * Y
__device__ __forceinline__ void mm2(const float* X, const float* Y, float* Z) {
    Z[0] = X[0]*Y[0] + X[1]*Y[2];
    Z[1] = X[0]*Y[1] + X[1]*Y[3];
    Z[2] = X[2]*Y[0] + X[3]*Y[2];
    Z[3] = X[2]*Y[1] + X[3]*Y[3];
}

// ---------------------------------------------------------------------------
// K0: precompute matrix powers + constant bias (1 thread)
// ---------------------------------------------------------------------------
__global__ void k_prep(const float* __restrict__ WA,
                       const float* __restrict__ bA,
                       const float* __restrict__ bB) {
    float A[4] = {WA[0], WA[1], WA[2], WA[3]};
    float A2[4], A4[4], M[4];
    mm2(A, A, A2); mm2(A2, A2, A4); mm2(A4, A4, M);   // A^8
    for (int i = 0; i < 4; i++) g_M[i] = M[i];
    for (int k = 1; k < 9; k++) {
        float N[4]; mm2(M, M, N);
        for (int i = 0; i < 4; i++) { M[i] = N[i]; g_M[k*4 + i] = N[i]; }
    }
    g_dc[0] = bA[0] + bB[0];
    g_dc[1] = bA[1] + bB[1];
}

// ---------------------------------------------------------------------------
// K1: per-chunk carry. Each block = one chunk of 2048 steps; each thread runs
// 8 contiguous steps (zero init), Kogge-Stone affine combine in shared.
// ---------------------------------------------------------------------------
__global__ void __launch_bounds__(TPB)
k_carry(const float* __restrict__ u,
        const float* __restrict__ WA,
        const float* __restrict__ WB,
        int Tlen) {
    __shared__ float sM[8 * 4];
    __shared__ float sv0[TPB], sv1[TPB];
    const int tid = threadIdx.x;
    if (tid < 32) sM[tid] = g_M[tid];

    const long base = (long)blockIdx.x * LCH + (long)tid * SUB;
    float4 ua = *(const float4*)(u + base);
    float4 ub = *(const float4*)(u + base + 4);
    float4 va = *(const float4*)(u + Tlen + base);
    float4 vb = *(const float4*)(u + Tlen + base + 4);

    const float a00 = WA[0], a01 = WA[1], a10 = WA[2], a11 = WA[3];
    const float w00 = WB[0], w01 = WB[1], w10 = WB[2], w11 = WB[3];
    const float c0 = g_dc[0], c1 = g_dc[1];

    float u0[8] = {ua.x, ua.y, ua.z, ua.w, ub.x, ub.y, ub.z, ub.w};
    float u1[8] = {va.x, va.y, va.z, va.w, vb.x, vb.y, vb.z, vb.w};

    float v0 = 0.f, v1 = 0.f;
#pragma unroll
    for (int i = 0; i < 8; i++) {
        float d0 = w00*u0[i] + w01*u1[i] + c0;
        float d1 = w10*u0[i] + w11*u1[i] + c1;
        float n0 = a00*v0 + a01*v1 + d0;
        float n1 = a10*v0 + a11*v1 + d1;
        v0 = n0; v1 = n1;
    }
    sv0[tid] = v0; sv1[tid] = v1;
    __syncthreads();

#pragma unroll
    for (int k = 0; k < 8; k++) {
        const int off = 1 << k;
        const float m00 = sM[k*4+0], m01 = sM[k*4+1], m10 = sM[k*4+2], m11 = sM[k*4+3];
        float n0 = 0.f, n1 = 0.f;
        const bool act = (tid >= off);
        if (act) {
            float p0 = sv0[tid - off], p1 = sv1[tid - off];
            n0 = m00*p0 + m01*p1 + sv0[tid];
            n1 = m10*p0 + m11*p1 + sv1[tid];
        }
        __syncthreads();
        if (act) { sv0[tid] = n0; sv1[tid] = n1; }
        __syncthreads();
    }

    if (tid == TPB - 1) {
        g_carry[blockIdx.x * 2 + 0] = sv0[tid];
        g_carry[blockIdx.x * 2 + 1] = sv1[tid];
    }
}

// ---------------------------------------------------------------------------
// K2: scan the 2048 chunk carries (1 block). Thread j handles chunks
// [8j, 8j+8); Kogge-Stone with multipliers (A^LCH)^(8*2^k); writes x_start.
// ---------------------------------------------------------------------------
__global__ void __launch_bounds__(TPB)
k_scan(const float* __restrict__ x0in) {
    __shared__ float sN[8 * 4];
    __shared__ float sAL[4];
    __shared__ float sv0[TPB], sv1[TPB];
    const int tid = threadIdx.x;

    if (tid == 0) {
        float AL[4];
        for (int i = 0; i < 4; i++) { AL[i] = g_M[8*4 + i]; sAL[i] = AL[i]; }
        float T2[4], T4[4], Q[4];
        mm2(AL, AL, T2); mm2(T2, T2, T4); mm2(T4, T4, Q);   // (A^L)^8
        for (int i = 0; i < 4; i++) sN[i] = Q[i];
        for (int k = 1; k < 8; k++) {
            float N2[4]; mm2(Q, Q, N2);
            for (int i = 0; i < 4; i++) { Q[i] = N2[i]; sN[k*4 + i] = N2[i]; }
        }
    }
    __syncthreads();

    const float al00 = sAL[0], al01 = sAL[1], al10 = sAL[2], al11 = sAL[3];
    const int base = tid * CPT;

    float v0 = 0.f, v1 = 0.f;
#pragma unroll
    for (int i = 0; i < CPT; i++) {
        float d0 = g_carry[(base + i) * 2 + 0];
        float d1 = g_carry[(base + i) * 2 + 1];
        float n0 = al00*v0 + al01*v1 + d0;
        float n1 = al10*v0 + al11*v1 + d1;
        v0 = n0; v1 = n1;
    }
    sv0[tid] = v0; sv1[tid] = v1;
    __syncthreads();

#pragma unroll
    for (int k = 0; k < 8; k++) {
        const int off = 1 << k;
        const float m00 = sN[k*4+0], m01 = sN[k*4+1], m10 = sN[k*4+2], m11 = sN[k*4+3];
        float n0 = 0.f, n1 = 0.f;
        const bool act = (tid >= off);
        if (act) {
            float p0 = sv0[tid - off], p1 = sv1[tid - off];
            n0 = m00*p0 + m01*p1 + sv0[tid];
            n1 = m10*p0 + m11*p1 + sv1[tid];
        }
        __syncthreads();
        if (act) { sv0[tid] = n0; sv1[tid] = n1; }
        __syncthreads();
    }

    // exclusive prefix for this thread's group
    float e0 = (tid == 0) ? 0.f : sv0[tid - 1];
    float e1 = (tid == 0) ? 0.f : sv1[tid - 1];

    // A^(8*LCH*tid) via binary expansion over sN (powers of same A commute)
    float P[4] = {1.f, 0.f, 0.f, 1.f};
#pragma unroll
    for (int k = 0; k < 8; k++) {
        if (tid & (1 << k)) {
            float Nk[4] = {sN[k*4+0], sN[k*4+1], sN[k*4+2], sN[k*4+3]};
            float Z[4]; mm2(P, Nk, Z);
            P[0]=Z[0]; P[1]=Z[1]; P[2]=Z[2]; P[3]=Z[3];
        }
    }

    const float x00 = x0in[0], x01 = x0in[1];
    float S0 = P[0]*x00 + P[1]*x01 + e0;
    float S1 = P[2]*x00 + P[3]*x01 + e1;

#pragma unroll
    for (int i = 0; i < CPT; i++) {
        g_xstart[(base + i) * 2 + 0] = S0;
        g_xstart[(base + i) * 2 + 1] = S1;
        float d0 = g_carry[(base + i) * 2 + 0];
        float d1 = g_carry[(base + i) * 2 + 1];
        float n0 = al00*S0 + al01*S1 + d0;
        float n1 = al10*S0 + al11*S1 + d1;
        S0 = n0; S1 = n1;
    }
}

// ---------------------------------------------------------------------------
// K3: output pass. Recompute local prefixes, reconstruct per-thread state,
// run 8 steps, emit out_t = x_{t-1} + g_t - x_t.
// ---------------------------------------------------------------------------
__global__ void __launch_bounds__(TPB)
k_out(const float* __restrict__ u,
      const float* __restrict__ dt,
      const float* __restrict__ WA,
      const float* __restrict__ WB,
      float* __restrict__ out,
      int Tlen) {
    __shared__ float sM[8 * 4];
    __shared__ float sv0[TPB], sv1[TPB];
    const int tid = threadIdx.x;
    if (tid < 32) sM[tid] = g_M[tid];

    const long base = (long)blockIdx.x * LCH + (long)tid * SUB;
    float4 ua = *(const float4*)(u + base);
    float4 ub = *(const float4*)(u + base + 4);
    float4 va = *(const float4*)(u + Tlen + base);
    float4 vb = *(const float4*)(u + Tlen + base + 4);
    float4 ta = *(const float4*)(dt + base);
    float4 tb = *(const float4*)(dt + base + 4);

    const float a00 = WA[0], a01 = WA[1], a10 = WA[2], a11 = WA[3];
    const float w00 = WB[0], w01 = WB[1], w10 = WB[2], w11 = WB[3];
    const float c0 = g_dc[0], c1 = g_dc[1];

    float u0[8] = {ua.x, ua.y, ua.z, ua.w, ub.x, ub.y, ub.z, ub.w};
    float u1[8] = {va.x, va.y, va.z, va.w, vb.x, vb.y, vb.z, vb.w};
    float dv[8] = {ta.x, ta.y, ta.z, ta.w, tb.x, tb.y, tb.z, tb.w};

    float d0a[8], d1a[8];
    float v0 = 0.f, v1 = 0.f;
#pragma unroll
    for (int i = 0; i < 8; i++) {
        float d0 = w00*u0[i] + w01*u1[i] + c0;
        float d1 = w10*u0[i] + w11*u1[i] + c1;
        d0a[i] = d0; d1a[i] = d1;
        float n0 = a00*v0 + a01*v1 + d0;
        float n1 = a10*v0 + a11*v1 + d1;
        v0 = n0; v1 = n1;
    }
    sv0[tid] = v0; sv1[tid] = v1;
    __syncthreads();

#pragma unroll
    for (int k = 0; k < 8; k++) {
        const int off = 1 << k;
        const float m00 = sM[k*4+0], m01 = sM[k*4+1], m10 = sM[k*4+2], m11 = sM[k*4+3];
        float n0 = 0.f, n1 = 0.f;
        const bool act = (tid >= off);
        if (act) {
            float p0 = sv0[tid - off], p1 = sv1[tid - off];
            n0 = m00*p0 + m01*p1 + sv0[tid];
            n1 = m10*p0 + m11*p1 + sv1[tid];
        }
        __syncthreads();
        if (act) { sv0[tid] = n0; sv1[tid] = n1; }
        __syncthreads();
    }

    float e0 = (tid == 0) ? 0.f : sv0[tid - 1];
    float e1 = (tid == 0) ? 0.f : sv1[tid - 1];

    // A^(8*tid) via binary expansion over sM
    float P[4] = {1.f, 0.f, 0.f, 1.f};
#pragma unroll
    for (int k = 0; k < 8; k++) {
        if (tid & (1 << k)) {
            float Mk[4] = {sM[k*4+0], sM[k*4+1], sM[k*4+2], sM[k*4+3]};
            float Z[4]; mm2(P, Mk, Z);
            P[0]=Z[0]; P[1]=Z[1]; P[2]=Z[2]; P[3]=Z[3];
        }
    }

    const float xs0 = g_xstart[blockIdx.x * 2 + 0];
    const float xs1 = g_xstart[blockIdx.x * 2 + 1];
    float S0 = P[0]*xs0 + P[1]*xs1 + e0;
    float S1 = P[2]*xs0 + P[3]*xs1 + e1;

    float o[16];
#pragma unroll
    for (int i = 0; i < 8; i++) {
        float ci = u0[i] * dv[i];
        float sn, cs;
        sincosf(u1[i], &sn, &cs);
        float n0 = a00*S0 + a01*S1 + d0a[i];
        float n1 = a10*S0 + a11*S1 + d1a[i];
        o[2*i + 0] = S0 + ci*cs - n0;
        o[2*i + 1] = S1 + ci*sn - n1;
        S0 = n0; S1 = n1;
    }

    float4* op = (float4*)(out + base * 2);
    op[0] = make_float4(o[0],  o[1],  o[2],  o[3]);
    op[1] = make_float4(o[4],  o[5],  o[6],  o[7]);
    op[2] = make_float4(o[8],  o[9],  o[10], o[11]);
    op[3] = make_float4(o[12], o[13], o[14], o[15]);
}

// ---------------------------------------------------------------------------
extern "C" void kernel_launch(void* const* d_in, const int* in_sizes, int n_in,
                              void* d_out, int out_size) {
    const float* x0 = (const float*)d_in[0];
    const float* u  = (const float*)d_in[1];
    const float* dt = (const float*)d_in[2];
    const float* WA = (const float*)d_in[3];
    const float* bA = (const float*)d_in[4];
    const float* WB = (const float*)d_in[5];
    const float* bB = (const float*)d_in[6];
    const int T = in_sizes[2];           // 4194304
    const int C = T / LCH;               // 2048 chunks

    k_prep<<<1, 1>>>(WA, bA, bB);
    k_carry<<<C, TPB>>>(u, WA, WB, T);
    k_scan<<<1, TPB>>>(x0);
    k_out<<<C, TPB>>>(u, dt, WA, WB, (float*)d_out, T);
}

// round 2
// speedup vs baseline: 1.1940x; 1.1940x over previous
#include <cuda_runtime.h>
#include <math.h>

#define TPB 256
#define SUB 8
#define LCH (TPB * SUB)      // 2048 steps per chunk
#define NCH 2048             // chunks: T / LCH  (T = 4194304)
#define CPT 8                // chunks per thread in k_scan (NCH / TPB)

// Scratch (device globals: no allocation allowed)
__device__ float g_carry[NCH * 2];
__device__ float g_xstart[NCH * 2];
__device__ float2 g_tpref[NCH * TPB];   // per-thread exclusive prefix (4 MB)
__device__ float g_M[9 * 4];            // g_M[k] = A^(8 * 2^k), k=0..8
__device__ float g_dc[2];               // b_A + b_B

__device__ __forceinline__ void mm2(const float* X, const float* Y, float* Z) {
    Z[0] = X[0]*Y[0] + X[1]*Y[2];
    Z[1] = X[0]*Y[1] + X[1]*Y[3];
    Z[2] = X[2]*Y[0] + X[3]*Y[2];
    Z[3] = X[2]*Y[1] + X[3]*Y[3];
}

// ---------------------------------------------------------------------------
// K0: precompute matrix powers + constant bias (1 thread)
// ---------------------------------------------------------------------------
__global__ void k_prep(const float* __restrict__ WA,
                       const float* __restrict__ bA,
                       const float* __restrict__ bB) {
    float A[4] = {WA[0], WA[1], WA[2], WA[3]};
    float A2[4], A4[4], M[4];
    mm2(A, A, A2); mm2(A2, A2, A4); mm2(A4, A4, M);   // A^8
    for (int i = 0; i < 4; i++) g_M[i] = M[i];
    for (int k = 1; k < 9; k++) {
        float N[4]; mm2(M, M, N);
        for (int i = 0; i < 4; i++) { M[i] = N[i]; g_M[k*4 + i] = N[i]; }
    }
    g_dc[0] = bA[0] + bB[0];
    g_dc[1] = bA[1] + bB[1];
}

// ---------------------------------------------------------------------------
// K1: per-chunk carry + per-thread exclusive prefixes.
// Warp-shuffle affine scan (5 rounds) + single cross-warp fold.
// ---------------------------------------------------------------------------
__global__ void __launch_bounds__(TPB)
k_carry(const float* __restrict__ u,
        const float* __restrict__ WA,
        const float* __restrict__ WB,
        int Tlen) {
    __shared__ float sM[8 * 4];
    __shared__ float2 swt[8];           // warp totals
    const int tid  = threadIdx.x;
    const int lane = tid & 31;
    const int wid  = tid >> 5;
    if (tid < 32) sM[tid] = g_M[tid];

    const long base = (long)blockIdx.x * LCH + (long)tid * SUB;
    float4 ua = *(const float4*)(u + base);
    float4 ub = *(const float4*)(u + base + 4);
    float4 va = *(const float4*)(u + Tlen + base);
    float4 vb = *(const float4*)(u + Tlen + base + 4);

    const float a00 = WA[0], a01 = WA[1], a10 = WA[2], a11 = WA[3];
    const float w00 = WB[0], w01 = WB[1], w10 = WB[2], w11 = WB[3];
    const float c0 = g_dc[0], c1 = g_dc[1];

    float u0[8] = {ua.x, ua.y, ua.z, ua.w, ub.x, ub.y, ub.z, ub.w};
    float u1[8] = {va.x, va.y, va.z, va.w, vb.x, vb.y, vb.z, vb.w};

    // local 8-step recurrence with zero init
    float v0 = 0.f, v1 = 0.f;
#pragma unroll
    for (int i = 0; i < 8; i++) {
        float d0 = w00*u0[i] + w01*u1[i] + c0;
        float d1 = w10*u0[i] + w11*u1[i] + c1;
        float n0 = a00*v0 + a01*v1 + d0;
        float n1 = a10*v0 + a11*v1 + d1;
        v0 = n0; v1 = n1;
    }
    __syncthreads();   // sM ready

    // warp-level inclusive affine scan, multipliers A^(8*2^k)
#pragma unroll
    for (int k = 0; k < 5; k++) {
        const int off = 1 << k;
        const float m00 = sM[k*4+0], m01 = sM[k*4+1], m10 = sM[k*4+2], m11 = sM[k*4+3];
        float p0 = __shfl_up_sync(0xffffffffu, v0, off);
        float p1 = __shfl_up_sync(0xffffffffu, v1, off);
        if (lane >= off) {
            v0 = m00*p0 + m01*p1 + v0;
            v1 = m10*p0 + m11*p1 + v1;
        }
    }

    // publish warp totals
    if (lane == 31) swt[wid] = make_float2(v0, v1);
    __syncthreads();

    // warp-exclusive carry E_w = sum_{w'<w} (A^256)^(w-1-w') tot_{w'}
    const float q00 = sM[5*4+0], q01 = sM[5*4+1], q10 = sM[5*4+2], q11 = sM[5*4+3]; // A^256
    float E0 = 0.f, E1 = 0.f;
#pragma unroll
    for (int w = 0; w < 7; w++) {
        if (w < wid) {
            float n0 = q00*E0 + q01*E1 + swt[w].x;
            float n1 = q10*E0 + q11*E1 + swt[w].y;
            E0 = n0; E1 = n1;
        }
    }

    // within-warp exclusive value
    float we0 = __shfl_up_sync(0xffffffffu, v0, 1);
    float we1 = __shfl_up_sync(0xffffffffu, v1, 1);
    if (lane == 0) { we0 = 0.f; we1 = 0.f; }

    // P_lane = A^(8*lane), binary expansion over sM[0..4]
    float P[4] = {1.f, 0.f, 0.f, 1.f};
#pragma unroll
    for (int k = 0; k < 5; k++) {
        if (lane & (1 << k)) {
            float Mk[4] = {sM[k*4+0], sM[k*4+1], sM[k*4+2], sM[k*4+3]};
            float Z[4]; mm2(P, Mk, Z);
            P[0]=Z[0]; P[1]=Z[1]; P[2]=Z[2]; P[3]=Z[3];
        }
    }

    // global exclusive prefix within chunk (zero-init chunk)
    float e0 = P[0]*E0 + P[1]*E1 + we0;
    float e1 = P[2]*E0 + P[3]*E1 + we1;
    g_tpref[blockIdx.x * TPB + tid] = make_float2(e0, e1);

    if (tid == TPB - 1) {
        // chunk carry = A^8 * exclusive + own local value
        const float a8_00 = sM[0], a8_01 = sM[1], a8_10 = sM[2], a8_11 = sM[3];
        g_carry[blockIdx.x * 2 + 0] = a8_00*e0 + a8_01*e1 + v0;
        g_carry[blockIdx.x * 2 + 1] = a8_10*e0 + a8_11*e1 + v1;
    }
}

// ---------------------------------------------------------------------------
// K2: scan the 2048 chunk carries (1 block), writes chunk start states.
// ---------------------------------------------------------------------------
__global__ void __launch_bounds__(TPB)
k_scan(const float* __restrict__ x0in) {
    __shared__ float sN[8 * 4];
    __shared__ float sAL[4];
    __shared__ float sv0[TPB], sv1[TPB];
    const int tid = threadIdx.x;

    if (tid == 0) {
        float AL[4];
        for (int i = 0; i < 4; i++) { AL[i] = g_M[8*4 + i]; sAL[i] = AL[i]; }
        float T2[4], T4[4], Q[4];
        mm2(AL, AL, T2); mm2(T2, T2, T4); mm2(T4, T4, Q);   // (A^L)^8
        for (int i = 0; i < 4; i++) sN[i] = Q[i];
        for (int k = 1; k < 8; k++) {
            float N2[4]; mm2(Q, Q, N2);
            for (int i = 0; i < 4; i++) { Q[i] = N2[i]; sN[k*4 + i] = N2[i]; }
        }
    }
    __syncthreads();

    const float al00 = sAL[0], al01 = sAL[1], al10 = sAL[2], al11 = sAL[3];
    const int base = tid * CPT;

    float v0 = 0.f, v1 = 0.f;
#pragma unroll
    for (int i = 0; i < CPT; i++) {
        float d0 = g_carry[(base + i) * 2 + 0];
        float d1 = g_carry[(base + i) * 2 + 1];
        float n0 = al00*v0 + al01*v1 + d0;
        float n1 = al10*v0 + al11*v1 + d1;
        v0 = n0; v1 = n1;
    }
    sv0[tid] = v0; sv1[tid] = v1;
    __syncthreads();

#pragma unroll
    for (int k = 0; k < 8; k++) {
        const int off = 1 << k;
        const float m00 = sN[k*4+0], m01 = sN[k*4+1], m10 = sN[k*4+2], m11 = sN[k*4+3];
        float n0 = 0.f, n1 = 0.f;
        const bool act = (tid >= off);
        if (act) {
            float p0 = sv0[tid - off], p1 = sv1[tid - off];
            n0 = m00*p0 + m01*p1 + sv0[tid];
            n1 = m10*p0 + m11*p1 + sv1[tid];
        }
        __syncthreads();
        if (act) { sv0[tid] = n0; sv1[tid] = n1; }
        __syncthreads();
    }

    float e0 = (tid == 0) ? 0.f : sv0[tid - 1];
    float e1 = (tid == 0) ? 0.f : sv1[tid - 1];

    // A^(8*LCH*tid) via binary expansion over sN
    float P[4] = {1.f, 0.f, 0.f, 1.f};
#pragma unroll
    for (int k = 0; k < 8; k++) {
        if (tid & (1 << k)) {
            float Nk[4] = {sN[k*4+0], sN[k*4+1], sN[k*4+2], sN[k*4+3]};
            float Z[4]; mm2(P, Nk, Z);
            P[0]=Z[0]; P[1]=Z[1]; P[2]=Z[2]; P[3]=Z[3];
        }
    }

    const float x00 = x0in[0], x01 = x0in[1];
    float S0 = P[0]*x00 + P[1]*x01 + e0;
    float S1 = P[2]*x00 + P[3]*x01 + e1;

#pragma unroll
    for (int i = 0; i < CPT; i++) {
        g_xstart[(base + i) * 2 + 0] = S0;
        g_xstart[(base + i) * 2 + 1] = S1;
        float d0 = g_carry[(base + i) * 2 + 0];
        float d1 = g_carry[(base + i) * 2 + 1];
        float n0 = al00*S0 + al01*S1 + d0;
        float n1 = al10*S0 + al11*S1 + d1;
        S0 = n0; S1 = n1;
    }
}

// ---------------------------------------------------------------------------
// K3: streaming output pass. No scans — start state reconstructed from the
// chunk start (g_xstart) and the stored per-thread exclusive prefix.
// ---------------------------------------------------------------------------
__global__ void __launch_bounds__(TPB)
k_out(const float* __restrict__ u,
      const float* __restrict__ dt,
      const float* __restrict__ WA,
      const float* __restrict__ WB,
      float* __restrict__ out,
      int Tlen) {
    __shared__ float sM[8 * 4];
    const int tid = threadIdx.x;
    if (tid < 32) sM[tid] = g_M[tid];

    const long base = (long)blockIdx.x * LCH + (long)tid * SUB;
    float4 ua = *(const float4*)(u + base);
    float4 ub = *(const float4*)(u + base + 4);
    float4 va = *(const float4*)(u + Tlen + base);
    float4 vb = *(const float4*)(u + Tlen + base + 4);
    float4 ta = *(const float4*)(dt + base);
    float4 tb = *(const float4*)(dt + base + 4);

    const float a00 = WA[0], a01 = WA[1], a10 = WA[2], a11 = WA[3];
    const float w00 = WB[0], w01 = WB[1], w10 = WB[2], w11 = WB[3];
    const float c0 = g_dc[0], c1 = g_dc[1];

    float u0[8] = {ua.x, ua.y, ua.z, ua.w, ub.x, ub.y, ub.z, ub.w};
    float u1[8] = {va.x, va.y, va.z, va.w, vb.x, vb.y, vb.z, vb.w};
    float dv[8] = {ta.x, ta.y, ta.z, ta.w, tb.x, tb.y, tb.z, tb.w};

    const float2 e = g_tpref[blockIdx.x * TPB + tid];
    const float xs0 = g_xstart[blockIdx.x * 2 + 0];
    const float xs1 = g_xstart[blockIdx.x * 2 + 1];

    __syncthreads();   // sM ready

    // P = A^(8*tid), binary expansion over sM[0..7]
    float P[4] = {1.f, 0.f, 0.f, 1.f};
#pragma unroll
    for (int k = 0; k < 8; k++) {
        if (tid & (1 << k)) {
            float Mk[4] = {sM[k*4+0], sM[k*4+1], sM[k*4+2], sM[k*4+3]};
            float Z[4]; mm2(P, Mk, Z);
            P[0]=Z[0]; P[1]=Z[1]; P[2]=Z[2]; P[3]=Z[3];
        }
    }

    float S0 = P[0]*xs0 + P[1]*xs1 + e.x;
    float S1 = P[2]*xs0 + P[3]*xs1 + e.y;

    float o[16];
#pragma unroll
    for (int i = 0; i < 8; i++) {
        float d0 = w00*u0[i] + w01*u1[i] + c0;
        float d1 = w10*u0[i] + w11*u1[i] + c1;
        float ci = u0[i] * dv[i];
        float sn, cs;
        __sincosf(u1[i], &sn, &cs);
        float n0 = a00*S0 + a01*S1 + d0;
        float n1 = a10*S0 + a11*S1 + d1;
        o[2*i + 0] = S0 + ci*cs - n0;
        o[2*i + 1] = S1 + ci*sn - n1;
        S0 = n0; S1 = n1;
    }

    float4* op = (float4*)(out + base * 2);
    op[0] = make_float4(o[0],  o[1],  o[2],  o[3]);
    op[1] = make_float4(o[4],  o[5],  o[6],  o[7]);
    op[2] = make_float4(o[8],  o[9],  o[10], o[11]);
    op[3] = make_float4(o[12], o[13], o[14], o[15]);
}

// ---------------------------------------------------------------------------
extern "C" void kernel_launch(void* const* d_in, const int* in_sizes, int n_in,
                              void* d_out, int out_size) {
    const float* x0 = (const float*)d_in[0];
    const float* u  = (const float*)d_in[1];
    const float* dt = (const float*)d_in[2];
    const float* WA = (const float*)d_in[3];
    const float* bA = (const float*)d_in[4];
    const float* WB = (const float*)d_in[5];
    const float* bB = (const float*)d_in[6];
    const int T = in_sizes[2];           // 4194304
    const int C = T / LCH;               // 2048 chunks

    k_prep<<<1, 1>>>(WA, bA, bB);
    k_carry<<<C, TPB>>>(u, WA, WB, T);
    k_scan<<<1, TPB>>>(x0);
    k_out<<<C, TPB>>>(u, dt, WA, WB, (float*)d_out, T);
}